// round 1
// baseline (speedup 1.0000x reference)
#include <cuda_runtime.h>

// POLLU RHS: dy[b][s] = sum_r S[s][r] * k[r] * C[a_r][b] * C[b_r][b]
// Input  conc: [20, B] species-major (row-contiguous)  -> coalesced loads
// Output dy  : [B, 20] batch-major                      -> smem-staged coalesced stores
//
// Entire stoichiometry + reaction index tables are compile-time constants,
// transcribed and unrolled below.

#define TILE 256

__global__ __launch_bounds__(TILE)
void pollu_kernel(const float* __restrict__ conc,
                  const float* __restrict__ k,
                  float* __restrict__ out,
                  int B)
{
    __shared__ float s_dy[TILE][21];   // +1 pad: conflict-light readback

    const int tid = threadIdx.x;
    const int b0  = blockIdx.x * TILE;
    const int b   = b0 + tid;
    const int n_valid = min(TILE, B - b0);

    if (b < B) {
        // ---- load 20 species (coalesced: stride-B rows) ----
        float C0  = __ldg(&conc[ 0*B + b]);
        float C1  = __ldg(&conc[ 1*B + b]);
        float C2  = __ldg(&conc[ 2*B + b]);
        float C3  = __ldg(&conc[ 3*B + b]);
        float C4  = __ldg(&conc[ 4*B + b]);
        float C5  = __ldg(&conc[ 5*B + b]);
        float C6  = __ldg(&conc[ 6*B + b]);
        float C8  = __ldg(&conc[ 8*B + b]);
        float C9  = __ldg(&conc[ 9*B + b]);
        float C10 = __ldg(&conc[10*B + b]);
        float C12 = __ldg(&conc[12*B + b]);
        float C13 = __ldg(&conc[13*B + b]);
        float C15 = __ldg(&conc[15*B + b]);
        float C16 = __ldg(&conc[16*B + b]);
        float C18 = __ldg(&conc[18*B + b]);
        float C19 = __ldg(&conc[19*B + b]);
        // species 7, 11, 14, 17 never appear as reactants

        // ---- 25 fluxes (k broadcast loads hit L1/const path) ----
        float r1  = __ldg(&k[ 0]) * C0;
        float r2  = __ldg(&k[ 1]) * C1  * C3;
        float r3  = __ldg(&k[ 2]) * C4  * C1;
        float r4  = __ldg(&k[ 3]) * C6;
        float r5  = __ldg(&k[ 4]) * C6;
        float r6  = __ldg(&k[ 5]) * C6  * C5;
        float r7  = __ldg(&k[ 6]) * C8;
        float r8  = __ldg(&k[ 7]) * C8  * C5;
        float r9  = __ldg(&k[ 8]) * C10 * C1;
        float r10 = __ldg(&k[ 9]) * C10 * C0;
        float r11 = __ldg(&k[10]) * C12;
        float r12 = __ldg(&k[11]) * C9  * C1;
        float r13 = __ldg(&k[12]) * C13;
        float r14 = __ldg(&k[13]) * C0  * C5;
        float r15 = __ldg(&k[14]) * C2;
        float r16 = __ldg(&k[15]) * C3;
        float r17 = __ldg(&k[16]) * C3;
        float r18 = __ldg(&k[17]) * C15;
        float r19 = __ldg(&k[18]) * C15;
        float r20 = __ldg(&k[19]) * C16 * C5;
        float r21 = __ldg(&k[20]) * C18;
        float r22 = __ldg(&k[21]) * C18;
        float r23 = __ldg(&k[22]) * C0  * C3;
        float r24 = __ldg(&k[23]) * C18 * C0;
        float r25 = __ldg(&k[24]) * C19;

        // ---- stoichiometry (fixed sparse S) ----
        s_dy[tid][ 0] = -r1 - r10 - r14 - r23 - r24 + r2 + r3 + r9 + r11 + r12 + r22 + r25;
        s_dy[tid][ 1] = -r2 - r3 - r9 - r12 + r1 + r21;
        s_dy[tid][ 2] = -r15 + r1 + r17 + r19 + r22;
        s_dy[tid][ 3] = -r2 - r16 - r17 - r23 + r15;
        s_dy[tid][ 4] = -r3 + 2.0f*r4 + r6 + r7 + r13 + r20;
        s_dy[tid][ 5] = -r6 - r8 - r14 - r20 + r3 + 2.0f*r18;
        s_dy[tid][ 6] = -r4 - r5 - r6 + r13;
        s_dy[tid][ 7] =  r4 + r5 + r6 + r7;
        s_dy[tid][ 8] = -r7 - r8;
        s_dy[tid][ 9] = -r12 + r7 + r9;
        s_dy[tid][10] = -r9 - r10 + r8 + r11;
        s_dy[tid][11] =  r9;
        s_dy[tid][12] = -r11 + r10;
        s_dy[tid][13] = -r13 + r12;
        s_dy[tid][14] =  r14;
        s_dy[tid][15] = -r18 - r19 + r16;
        s_dy[tid][16] = -r20;
        s_dy[tid][17] =  r20;
        s_dy[tid][18] = -r21 - r22 - r24 + r23 + r25;
        s_dy[tid][19] = -r25 + r24;
    }
    __syncthreads();

    // ---- coalesced linear stream of the tile's contiguous output span ----
    const int total = n_valid * 20;
    float* obase = out + (long long)b0 * 20;
    #pragma unroll 5
    for (int j = tid; j < total; j += TILE) {
        obase[j] = s_dy[j / 20][j % 20];
    }
}

extern "C" void kernel_launch(void* const* d_in, const int* in_sizes, int n_in,
                              void* d_out, int out_size)
{
    // inputs per metadata order: t [1], conc_in [20*B], k [25]
    const float* conc = (const float*)d_in[1];
    const float* k    = (const float*)d_in[2];
    float* out        = (float*)d_out;
    const int B = in_sizes[1] / 20;

    const int grid = (B + TILE - 1) / TILE;
    pollu_kernel<<<grid, TILE>>>(conc, k, out, B);
}

// round 2
// speedup vs baseline: 1.3110x; 1.3110x over previous
#include <cuda_runtime.h>
#include <cstdint>

// POLLU RHS: dy[b][s] = sum_r S[s][r] * k[r] * C[a_r][b] * C[b_r][b]
// Input  conc: [20, B] species-major -> coalesced scalar LDG (128B/warp/species)
// Output dy  : [B, 20] batch-major   -> staged in UNPADDED smem [TILE][20],
//              drained by a single 1-D TMA bulk store (cp.async.bulk) per block.
//
// L1TEX budget/column: LDG 80B + STS 80B (conflict-free 5x STS.128) + bulk read 80B.
// (Previous version also pushed 80B LDS + 80B STG through L1TEX -> was L1-bound.)

#define TILE 256

__global__ __launch_bounds__(TILE)
void pollu_kernel(const float* __restrict__ conc,
                  const float* __restrict__ k,
                  float* __restrict__ out,
                  int B)
{
    // Unpadded, contiguous: TILE rows x 20 floats = TILE*80 bytes.
    __shared__ __align__(16) float s_dy[TILE * 20];

    const int tid = threadIdx.x;
    const int b0  = blockIdx.x * TILE;
    const int b   = b0 + tid;
    const int n_valid = min(TILE, B - b0);

    if (b < B) {
        // ---- coalesced loads: 20 species rows, stride B ----
        float C0  = __ldg(&conc[ 0*B + b]);
        float C1  = __ldg(&conc[ 1*B + b]);
        float C2  = __ldg(&conc[ 2*B + b]);
        float C3  = __ldg(&conc[ 3*B + b]);
        float C4  = __ldg(&conc[ 4*B + b]);
        float C5  = __ldg(&conc[ 5*B + b]);
        float C6  = __ldg(&conc[ 6*B + b]);
        float C8  = __ldg(&conc[ 8*B + b]);
        float C9  = __ldg(&conc[ 9*B + b]);
        float C10 = __ldg(&conc[10*B + b]);
        float C12 = __ldg(&conc[12*B + b]);
        float C13 = __ldg(&conc[13*B + b]);
        float C15 = __ldg(&conc[15*B + b]);
        float C16 = __ldg(&conc[16*B + b]);
        float C18 = __ldg(&conc[18*B + b]);
        float C19 = __ldg(&conc[19*B + b]);

        // ---- 25 fluxes ----
        float r1  = __ldg(&k[ 0]) * C0;
        float r2  = __ldg(&k[ 1]) * C1  * C3;
        float r3  = __ldg(&k[ 2]) * C4  * C1;
        float r4  = __ldg(&k[ 3]) * C6;
        float r5  = __ldg(&k[ 4]) * C6;
        float r6  = __ldg(&k[ 5]) * C6  * C5;
        float r7  = __ldg(&k[ 6]) * C8;
        float r8  = __ldg(&k[ 7]) * C8  * C5;
        float r9  = __ldg(&k[ 8]) * C10 * C1;
        float r10 = __ldg(&k[ 9]) * C10 * C0;
        float r11 = __ldg(&k[10]) * C12;
        float r12 = __ldg(&k[11]) * C9  * C1;
        float r13 = __ldg(&k[12]) * C13;
        float r14 = __ldg(&k[13]) * C0  * C5;
        float r15 = __ldg(&k[14]) * C2;
        float r16 = __ldg(&k[15]) * C3;
        float r17 = __ldg(&k[16]) * C3;
        float r18 = __ldg(&k[17]) * C15;
        float r19 = __ldg(&k[18]) * C15;
        float r20 = __ldg(&k[19]) * C16 * C5;
        float r21 = __ldg(&k[20]) * C18;
        float r22 = __ldg(&k[21]) * C18;
        float r23 = __ldg(&k[22]) * C0  * C3;
        float r24 = __ldg(&k[23]) * C18 * C0;
        float r25 = __ldg(&k[24]) * C19;

        // ---- stoichiometry into registers ----
        float d0  = -r1 - r10 - r14 - r23 - r24 + r2 + r3 + r9 + r11 + r12 + r22 + r25;
        float d1  = -r2 - r3 - r9 - r12 + r1 + r21;
        float d2  = -r15 + r1 + r17 + r19 + r22;
        float d3  = -r2 - r16 - r17 - r23 + r15;
        float d4  = -r3 + 2.0f*r4 + r6 + r7 + r13 + r20;
        float d5  = -r6 - r8 - r14 - r20 + r3 + 2.0f*r18;
        float d6  = -r4 - r5 - r6 + r13;
        float d7  =  r4 + r5 + r6 + r7;
        float d8  = -r7 - r8;
        float d9  = -r12 + r7 + r9;
        float d10 = -r9 - r10 + r8 + r11;
        float d11 =  r9;
        float d12 = -r11 + r10;
        float d13 = -r13 + r12;
        float d14 =  r14;
        float d15 = -r18 - r19 + r16;
        float d16 = -r20;
        float d17 =  r20;
        float d18 = -r21 - r22 - r24 + r23 + r25;
        float d19 = -r25 + r24;

        // ---- 5x STS.128, conflict-free in unpadded [TILE][20] layout ----
        // chunk address (16B units) = 5*tid + j ; per 8-lane phase banks cover
        // {0,20,8,28,16,4,24,12}·(+0..3) = all 32 banks, disjoint.
        float4* srow = reinterpret_cast<float4*>(&s_dy[tid * 20]);
        srow[0] = make_float4(d0,  d1,  d2,  d3);
        srow[1] = make_float4(d4,  d5,  d6,  d7);
        srow[2] = make_float4(d8,  d9,  d10, d11);
        srow[3] = make_float4(d12, d13, d14, d15);
        srow[4] = make_float4(d16, d17, d18, d19);
    }
    __syncthreads();

    // ---- single 1-D TMA bulk store of the block's contiguous output span ----
    if (tid == 0) {
        // order generic-proxy smem writes before the async-proxy bulk read
        asm volatile("fence.proxy.async.shared::cta;" ::: "memory");

        uint32_t smem_addr;
        asm("{ .reg .u64 t; cvta.to.shared.u64 t, %1; cvt.u32.u64 %0, t; }"
            : "=r"(smem_addr) : "l"(s_dy));

        float* gdst = out + (long long)b0 * 20;
        unsigned bytes = (unsigned)(n_valid * 20 * sizeof(float));  // multiple of 16

        asm volatile(
            "cp.async.bulk.global.shared::cta.bulk_group [%0], [%1], %2;"
            :: "l"(gdst), "r"(smem_addr), "r"(bytes)
            : "memory");
        asm volatile("cp.async.bulk.commit_group;" ::: "memory");
        asm volatile("cp.async.bulk.wait_group 0;" ::: "memory");
    }
}

extern "C" void kernel_launch(void* const* d_in, const int* in_sizes, int n_in,
                              void* d_out, int out_size)
{
    // inputs per metadata order: t [1], conc_in [20*B], k [25]
    const float* conc = (const float*)d_in[1];
    const float* k    = (const float*)d_in[2];
    float* out        = (float*)d_out;
    const int B = in_sizes[1] / 20;

    const int grid = (B + TILE - 1) / TILE;
    pollu_kernel<<<grid, TILE>>>(conc, k, out, B);
}